// round 1
// baseline (speedup 1.0000x reference)
#include <cuda_runtime.h>
#include <cuda_bf16.h>
#include <cstdint>

// BilateralFilter (SqueezeSeg): out[b,z,a,k,c] = exp(-||x[b,z,a]-nbr_k||^2 / (2*theta_c^2))
// B=16, Z=64, A=512, C_in=3, K=14 (3x5 window minus center), NUM_CLASS=4
// theta = [0.015, 0.015, 0.01, 0.01]  -> only 2 distinct exps per (pixel,k)

#define BB 16
#define ZZ 64
#define AA 512
#define KK 14

#define TZ 8
#define TA 64
#define HZ (TZ + 2)   // 10
#define HA (TA + 4)   // 68

__global__ __launch_bounds__(TZ * TA, 2)
void bilateral_kernel(const float* __restrict__ x, float* __restrict__ out)
{
    __shared__ float4 tile[HZ][HA];   // 10*68*16 = 10880 B

    const int tid = threadIdx.x;
    const int a0 = blockIdx.x * TA;
    const int z0 = blockIdx.y * TZ;
    const int b  = blockIdx.z;

    // ---- cooperative halo load (zero padding outside image, per batch) ----
    #pragma unroll
    for (int idx = tid; idx < HZ * HA; idx += TZ * TA) {
        const int hz = idx / HA;
        const int ha = idx - hz * HA;
        const int gz = z0 + hz - 1;
        const int ga = a0 + ha - 2;
        float4 v = make_float4(0.f, 0.f, 0.f, 0.f);
        if (gz >= 0 && gz < ZZ && ga >= 0 && ga < AA) {
            const float* p = x + ((size_t)((b * ZZ + gz) * AA + ga)) * 3;
            v.x = p[0]; v.y = p[1]; v.z = p[2];
        }
        tile[hz][ha] = v;
    }
    __syncthreads();

    // ---- per-pixel compute ----
    const int tz = tid >> 6;        // 0..7
    const int ta = tid & 63;        // 0..63
    const int gz = z0 + tz;
    const int ga = a0 + ta;

    const float4 c = tile[tz + 1][ta + 2];

    // -1/(2*theta^2) * 1 ; __expf(d2 * C) = exp(-d2/(2 theta^2))
    const float C1 = -1.0f / (2.0f * 0.015f * 0.015f);  // classes 0,1
    const float C2 = -1.0f / (2.0f * 0.01f  * 0.01f );  // classes 2,3

    float4* ob = reinterpret_cast<float4*>(
        out + ((size_t)((b * ZZ + gz) * AA + ga)) * (KK * 4));

    int k = 0;
    #pragma unroll
    for (int i = 0; i < 3; ++i) {
        #pragma unroll
        for (int j = 0; j < 5; ++j) {
            if (i == 1 && j == 2) continue;   // skip center
            const float4 n = tile[tz + i][ta + j];
            const float dx = c.x - n.x;
            const float dy = c.y - n.y;
            const float dz = c.z - n.z;
            float d2 = dx * dx;
            d2 = fmaf(dy, dy, d2);
            d2 = fmaf(dz, dz, d2);
            const float e1 = __expf(d2 * C1);
            const float e2 = __expf(d2 * C2);
            ob[k] = make_float4(e1, e1, e2, e2);
            ++k;
        }
    }
}

extern "C" void kernel_launch(void* const* d_in, const int* in_sizes, int n_in,
                              void* d_out, int out_size)
{
    (void)in_sizes; (void)n_in; (void)out_size;
    const float* x = (const float*)d_in[0];
    float* out = (float*)d_out;

    dim3 grid(AA / TA, ZZ / TZ, BB);   // 8 x 8 x 16 = 1024 CTAs
    dim3 block(TZ * TA);               // 512 threads
    bilateral_kernel<<<grid, block>>>(x, out);
}

// round 2
// speedup vs baseline: 1.0394x; 1.0394x over previous
#include <cuda_runtime.h>
#include <cuda_bf16.h>
#include <cstdint>

// BilateralFilter (SqueezeSeg): out[b,z,a,k,c] = exp(-||x[b,z,a]-nbr_k||^2 / (2*theta_c^2))
// B=16, Z=64, A=512, C_in=3, K=14 (3x5 minus center), NUM_CLASS=4
// theta = [0.015,0.015,0.01,0.01] -> per (pixel,k) output float4 = (e1,e1,e2,e2)
//
// R2: one thread per OUTPUT float4 (pixel,k). tid = p*14 + k, so consecutive
// lanes write consecutive float4 -> fully coalesced STG.128 (4 wavefronts/inst
// instead of 32 in R1's thread-per-pixel layout).

#define BB 16
#define ZZ 64
#define AA 512
#define KK 14

#define TA 64                 // pixels (along a) per block
#define NT (TA * KK)          // 896 threads
#define HW (TA + 4)           // 68 halo width

__global__ __launch_bounds__(NT, 2)
void bilateral_kernel(const float* __restrict__ x, float4* __restrict__ out)
{
    __shared__ float4 tile[3][HW];   // 3 z-rows halo, 3*68*16 = 3264 B

    const int tid = threadIdx.x;
    const int a0 = blockIdx.x * TA;
    const int z  = blockIdx.y;
    const int b  = blockIdx.z;

    // ---- halo load: rows z-1..z+1, cols a0-2..a0+TA+1, zero padded ----
    if (tid < 3 * HW) {
        const int r = tid / HW;
        const int c = tid - r * HW;
        const int gz = z + r - 1;
        const int ga = a0 + c - 2;
        float4 v = make_float4(0.f, 0.f, 0.f, 0.f);
        if (gz >= 0 && gz < ZZ && ga >= 0 && ga < AA) {
            const float* p = x + ((size_t)((b * ZZ + gz) * AA + ga)) * 3;
            v.x = p[0]; v.y = p[1]; v.z = p[2];
        }
        tile[r][c] = v;
    }
    __syncthreads();

    // ---- one output float4 per thread ----
    const int p = tid / KK;           // pixel within tile: 0..63
    const int k = tid - p * KK;       // neighbor index:    0..13
    const int kk = k + (k >= 7);      // skip center (i=1,j=2 -> flat 7)
    const int i = kk / 5;             // 0..2
    const int j = kk - i * 5;         // 0..4

    const float4 c4 = tile[1][p + 2];     // broadcast across the 14 k-lanes
    const float4 n4 = tile[i][p + j];

    const float dx = c4.x - n4.x;
    const float dy = c4.y - n4.y;
    const float dz = c4.z - n4.z;
    const float d2 = fmaf(dz, dz, fmaf(dy, dy, dx * dx));

    const float C1 = -1.0f / (2.0f * 0.015f * 0.015f);  // classes 0,1
    const float C2 = -1.0f / (2.0f * 0.01f  * 0.01f );  // classes 2,3
    const float e1 = __expf(d2 * C1);
    const float e2 = __expf(d2 * C2);

    // out float4 index: ((b*ZZ+z)*AA + a0 + p)*KK + k = base + tid  (coalesced)
    const size_t base = ((size_t)((b * ZZ + z) * AA + a0)) * KK;
    out[base + tid] = make_float4(e1, e1, e2, e2);
}

extern "C" void kernel_launch(void* const* d_in, const int* in_sizes, int n_in,
                              void* d_out, int out_size)
{
    (void)in_sizes; (void)n_in; (void)out_size;
    const float* x = (const float*)d_in[0];
    float4* out = (float4*)d_out;

    dim3 grid(AA / TA, ZZ, BB);   // 8 x 64 x 16 = 8192 CTAs
    dim3 block(NT);               // 896 threads
    bilateral_kernel<<<grid, block>>>(x, out);
}

// round 4
// speedup vs baseline: 1.4883x; 1.4319x over previous
#include <cuda_runtime.h>
#include <cuda_bf16.h>
#include <cstdint>

// BilateralFilter (SqueezeSeg): out[b,z,a,k,c] = exp(-||x[b,z,a]-nbr_k||^2 / (2*theta_c^2))
// B=16, Z=64, A=512, K=14 (3x5 minus center), theta=[.015,.015,.01,.01]
// -> per (pixel,k) output float4 = (e1,e1,e2,e2), only 2 distinct exps.
//
// R3 resubmit (R3 bench died to container infra failure, no data produced).
// 4 outputs per thread. CTA = 256 pixels x 14 k = 3584 outputs / 896 thr.
// Stride 896 = 64*14 -> k and (i,j) are loop-invariant; p += 64 per iter.
// Stores stay fully coalesced (consecutive lanes -> consecutive float4).

#define BB 16
#define ZZ 64
#define AA 512
#define KK 14

#define TA 256                // pixels per CTA
#define NT 896                // threads
#define PT (TA / 64)          // 4 outputs per thread
#define HW (TA + 4)           // 260 halo width

__global__ __launch_bounds__(NT, 2)
void bilateral_kernel(const float* __restrict__ x, float4* __restrict__ out)
{
    __shared__ float4 tile[3][HW];   // 3 z-rows halo, 3*260*16 = 12480 B

    const int tid = threadIdx.x;
    const int a0 = blockIdx.x * TA;
    const int z  = blockIdx.y;
    const int b  = blockIdx.z;

    // ---- halo load: rows z-1..z+1, cols a0-2..a0+TA+1, zero padded ----
    if (tid < 3 * HW) {
        const int r = tid / HW;
        const int c = tid - r * HW;
        const int gz = z + r - 1;
        const int ga = a0 + c - 2;
        float4 v = make_float4(0.f, 0.f, 0.f, 0.f);
        if (gz >= 0 && gz < ZZ && ga >= 0 && ga < AA) {
            const float* p = x + ((size_t)((b * ZZ + gz) * AA + ga)) * 3;
            v.x = p[0]; v.y = p[1]; v.z = p[2];
        }
        tile[r][c] = v;
    }
    __syncthreads();

    // ---- decode once: k, (i,j) invariant across the 4 outputs ----
    const int p0 = tid / KK;          // 0..63
    const int k  = tid - p0 * KK;     // 0..13
    const int kk = k + (k >= 7);      // skip center (flat 7)
    const int i  = kk / 5;            // 0..2
    const int j  = kk - i * 5;        // 0..4

    // exp(-d2/(2 th^2)) = exp2f(d2 * C), C = -log2(e)/(2 th^2)
    const float L1 = -1.4426950408889634f / (2.0f * 0.015f * 0.015f);
    const float L2 = -1.4426950408889634f / (2.0f * 0.01f  * 0.01f );

    // out float4 index: ((b*ZZ+z)*AA + a0 + p)*KK + k = base + tid + it*NT
    float4* ob = out + ((size_t)((b * ZZ + z) * AA + a0)) * KK + tid;

    #pragma unroll
    for (int it = 0; it < PT; ++it) {
        const int p = p0 + it * 64;
        const float4 c4 = tile[1][p + 2];
        const float4 n4 = tile[i][p + j];
        const float dx = c4.x - n4.x;
        const float dy = c4.y - n4.y;
        const float dz = c4.z - n4.z;
        const float d2 = fmaf(dz, dz, fmaf(dy, dy, dx * dx));
        const float e1 = exp2f(d2 * L1);
        const float e2 = exp2f(d2 * L2);
        ob[it * NT] = make_float4(e1, e1, e2, e2);
    }
}

extern "C" void kernel_launch(void* const* d_in, const int* in_sizes, int n_in,
                              void* d_out, int out_size)
{
    (void)in_sizes; (void)n_in; (void)out_size;
    const float* x = (const float*)d_in[0];
    float4* out = (float4*)d_out;

    dim3 grid(AA / TA, ZZ, BB);   // 2 x 64 x 16 = 2048 CTAs
    dim3 block(NT);               // 896 threads
    bilateral_kernel<<<grid, block>>>(x, out);
}

// round 5
// speedup vs baseline: 1.7057x; 1.1460x over previous
#include <cuda_runtime.h>
#include <cuda_bf16.h>
#include <cstdint>

// BilateralFilter (SqueezeSeg): out[b,z,a,k,c] = exp(-||x[b,z,a]-nbr_k||^2 / (2*theta_c^2))
// B=16, Z=64, A=512, K=14 (3x5 minus center), theta=[.015,.015,.01,.01]
// -> per (pixel,k) output float4 = (e1,e1,e2,e2), only 2 distinct exps.
//
// R5: persistent z-march. CTA = 256 a-pixels x 8 z-rows, 4-slot circular smem
// row buffer, register-prefetch of row z+2 overlapped with compute of row z.
// grid = 256 CTAs @ 896 thr -> single wave (2 CTAs/SM). Stores coalesced as R4.

#define BB 16
#define ZZ 64
#define AA 512
#define KK 14

#define TA 256                // pixels (a) per CTA
#define NT 896                // threads
#define PT 4                  // outputs per thread per z-step (TA*KK/NT)
#define HW (TA + 4)           // 260 halo width
#define ZC 8                  // z-rows per CTA

__global__ __launch_bounds__(NT, 2)
void bilateral_kernel(const float* __restrict__ x, float4* __restrict__ out)
{
    __shared__ float4 tile[4][HW];   // circular rows, slot = z & 3 ; 16640 B

    const int tid = threadIdx.x;
    const int a0 = blockIdx.x * TA;
    const int z0 = blockIdx.y * ZC;
    const int b  = blockIdx.z;

    // ---- prologue: load rows z0-1, z0, z0+1 into their slots ----
    for (int idx = tid; idx < 3 * HW; idx += NT) {
        const int r = idx / HW;
        const int c = idx - r * HW;
        const int gz = z0 + r - 1;
        const int ga = a0 + c - 2;
        float4 v = make_float4(0.f, 0.f, 0.f, 0.f);
        if (gz >= 0 && gz < ZZ && ga >= 0 && ga < AA) {
            const float* p = x + ((size_t)((b * ZZ + gz) * AA + ga)) * 3;
            v.x = p[0]; v.y = p[1]; v.z = p[2];
        }
        tile[gz & 3][c] = v;
    }
    __syncthreads();

    // ---- decode once: k, (i,j) invariant for this thread ----
    const int p0 = tid / KK;          // 0..63
    const int k  = tid - p0 * KK;     // 0..13
    const int kk = k + (k >= 7);      // skip center (flat 7)
    const int i  = kk / 5;            // 0..2
    const int j  = kk - i * 5;        // 0..4

    // exp(-d2/(2 th^2)) = exp2f(d2 * C), C = -log2(e)/(2 th^2)
    const float L1 = -1.4426950408889634f / (2.0f * 0.015f * 0.015f);
    const float L2 = -1.4426950408889634f / (2.0f * 0.01f  * 0.01f );

    float4* ob = out + ((size_t)((b * ZZ + z0) * AA + a0)) * KK + tid;

    #pragma unroll 1
    for (int z = z0; z < z0 + ZC; ++z) {
        // ---- register-prefetch row z+2 (hidden under this z's compute) ----
        float px = 0.f, py = 0.f, pz = 0.f;
        const bool doPre = (z + 2 <= z0 + ZC) && (tid < HW);
        if (doPre) {
            const int gz = z + 2;
            const int ga = a0 + tid - 2;
            if (gz < ZZ && ga >= 0 && ga < AA) {
                const float* p = x + ((size_t)((b * ZZ + gz) * AA + ga)) * 3;
                px = p[0]; py = p[1]; pz = p[2];
            }
        }

        // ---- compute row z ----
        const int sc = z & 3;             // center row slot
        const int sn = (z - 1 + i) & 3;   // neighbor row slot (i thread-const)
        #pragma unroll
        for (int it = 0; it < PT; ++it) {
            const int p = p0 + it * 64;
            const float4 c4 = tile[sc][p + 2];
            const float4 n4 = tile[sn][p + j];
            const float dx = c4.x - n4.x;
            const float dy = c4.y - n4.y;
            const float dz = c4.z - n4.z;
            const float d2 = fmaf(dz, dz, fmaf(dy, dy, dx * dx));
            const float e1 = exp2f(d2 * L1);
            const float e2 = exp2f(d2 * L2);
            ob[it * NT] = make_float4(e1, e1, e2, e2);
        }

        __syncthreads();                       // readers of slot (z+2)&3 done
        if (doPre)
            tile[(z + 2) & 3][tid] = make_float4(px, py, pz, 0.f);
        __syncthreads();                       // row z+2 visible for next step

        ob += (size_t)AA * KK;
    }
}

extern "C" void kernel_launch(void* const* d_in, const int* in_sizes, int n_in,
                              void* d_out, int out_size)
{
    (void)in_sizes; (void)n_in; (void)out_size;
    const float* x = (const float*)d_in[0];
    float4* out = (float4*)d_out;

    dim3 grid(AA / TA, ZZ / ZC, BB);   // 2 x 8 x 16 = 256 CTAs (single wave)
    dim3 block(NT);                    // 896 threads
    bilateral_kernel<<<grid, block>>>(x, out);
}

// round 6
// speedup vs baseline: 2.0079x; 1.1772x over previous
#include <cuda_runtime.h>
#include <cuda_bf16.h>
#include <cstdint>

// BilateralFilter (SqueezeSeg): out[b,z,a,k,c] = exp(-||x[b,z,a]-nbr_k||^2 / (2*theta_c^2))
// B=16, Z=64, A=512, K=14 (3x5 minus center), theta=[.015,.015,.01,.01]
// -> per (pixel,k) output float4 = (e1,e1,e2,e2), only 2 distinct exps.
//
// R6: R5 persistent z-march +
//   (1) single barrier per z-step (STS slot disjoint from compute slots),
//   (2) prefetch LDG one full z-step ahead (row z+3 issued at step z),
//   (3) __stcs streaming stores (output is write-once, keep input in L2).

#define BB 16
#define ZZ 64
#define AA 512
#define KK 14

#define TA 256                // pixels (a) per CTA
#define NT 896                // threads
#define PT 4                  // outputs per thread per z-step
#define HW (TA + 4)           // 260 halo width
#define ZC 8                  // z-rows per CTA

__global__ __launch_bounds__(NT, 2)
void bilateral_kernel(const float* __restrict__ x, float4* __restrict__ out)
{
    __shared__ float4 tile[4][HW];   // circular rows, slot = z & 3

    const int tid = threadIdx.x;
    const int a0 = blockIdx.x * TA;
    const int z0 = blockIdx.y * ZC;
    const int b  = blockIdx.z;

    // ---- prologue: rows z0-1, z0, z0+1 into their slots ----
    for (int idx = tid; idx < 3 * HW; idx += NT) {
        const int r = idx / HW;
        const int c = idx - r * HW;
        const int gz = z0 + r - 1;
        const int ga = a0 + c - 2;
        float4 v = make_float4(0.f, 0.f, 0.f, 0.f);
        if (gz >= 0 && gz < ZZ && ga >= 0 && ga < AA) {
            const float* p = x + ((size_t)((b * ZZ + gz) * AA + ga)) * 3;
            v.x = p[0]; v.y = p[1]; v.z = p[2];
        }
        tile[gz & 3][c] = v;
    }

    // ---- decode once: k, (i,j) invariant for this thread ----
    const int p0 = tid / KK;          // 0..63
    const int k  = tid - p0 * KK;     // 0..13
    const int kk = k + (k >= 7);      // skip center (flat 7)
    const int i  = kk / 5;            // 0..2
    const int j  = kk - i * 5;        // 0..4

    const float L1 = -1.4426950408889634f / (2.0f * 0.015f * 0.015f);
    const float L2 = -1.4426950408889634f / (2.0f * 0.01f  * 0.01f );

    float4* ob = out + ((size_t)((b * ZZ + z0) * AA + a0)) * KK + tid;

    // ---- initial register prefetch of row z0+2 ----
    const int ga_pf = a0 + tid - 2;
    const bool lane_pf = (tid < HW) && (ga_pf >= 0) && (ga_pf < AA);
    float px = 0.f, py = 0.f, pz = 0.f;
    {
        const int gz = z0 + 2;
        if (lane_pf && gz < ZZ) {
            const float* p = x + ((size_t)((b * ZZ + gz) * AA + ga_pf)) * 3;
            px = p[0]; py = p[1]; pz = p[2];
        }
    }

    #pragma unroll 1
    for (int z = z0; z < z0 + ZC; ++z) {
        __syncthreads();   // orders prior STS before this step's reads,
                           // and prior reads of slot (z+2)&3 before this STS

        // ---- STS prefetched row z+2 (slot disjoint from compute slots) ----
        if (tid < HW && z + 2 <= z0 + ZC)
            tile[(z + 2) & 3][tid] = make_float4(px, py, pz, 0.f);

        // ---- issue LDG prefetch for row z+3 (consumed next step) ----
        px = 0.f; py = 0.f; pz = 0.f;
        {
            const int gz = z + 3;
            if (lane_pf && gz <= z0 + ZC + 1 && gz < ZZ && z + 3 <= z0 + ZC) {
                const float* p = x + ((size_t)((b * ZZ + gz) * AA + ga_pf)) * 3;
                px = p[0]; py = p[1]; pz = p[2];
            }
        }

        // ---- compute row z (reads slots (z-1..z+1)&3 only) ----
        const int sc = z & 3;
        const int sn = (z - 1 + i) & 3;
        #pragma unroll
        for (int it = 0; it < PT; ++it) {
            const int p = p0 + it * 64;
            const float4 c4 = tile[sc][p + 2];
            const float4 n4 = tile[sn][p + j];
            const float dx = c4.x - n4.x;
            const float dy = c4.y - n4.y;
            const float dz = c4.z - n4.z;
            const float d2 = fmaf(dz, dz, fmaf(dy, dy, dx * dx));
            const float e1 = exp2f(d2 * L1);
            const float e2 = exp2f(d2 * L2);
            __stcs(&ob[it * NT], make_float4(e1, e1, e2, e2));
        }

        ob += (size_t)AA * KK;
    }
}

extern "C" void kernel_launch(void* const* d_in, const int* in_sizes, int n_in,
                              void* d_out, int out_size)
{
    (void)in_sizes; (void)n_in; (void)out_size;
    const float* x = (const float*)d_in[0];
    float4* out = (float4*)d_out;

    dim3 grid(AA / TA, ZZ / ZC, BB);   // 2 x 8 x 16 = 256 CTAs (single wave)
    dim3 block(NT);                    // 896 threads
    bilateral_kernel<<<grid, block>>>(x, out);
}